// round 10
// baseline (speedup 1.0000x reference)
#include <cuda_runtime.h>

// DilateAttention: B=8, C=384 (12 heads x 32), H=W=56, kernel 3x3, dilation 2, pad 2.
// q,k,v: [B, C, H, W] f32. out: [B, H, W, C] f32.
//
// R10 = R7 (2 px/thread, float2 window loads, CC=8) made fully BRANCHLESS via
// clamped offsets: invalid windows load from the (always-valid) center offset,
// and their contribution is zeroed by a float mask — once before softmax
// (logit -> 0, matching unfold zero-padding) and once after (weight -> 0, since
// OOB v is 0). No branches in the hot loops means ptxas can batch loads across
// all 9 windows -> ~4x the per-warp MLP of the guarded version (the measured
// issue-limiter across R5/R7/R9). NTHR=128 fixes block-granularity occupancy.

#define HD     32
#define HEADS  12
#define WD     56
#define HT     56
#define BD     8
#define HW     (WD * HT)
#define CTOT   384
#define XG     28          // x-pairs per row
#define NTHR   128
#define CC     8
#define NCH    (HD / CC)   // 4

__global__ __launch_bounds__(NTHR, 8)
void dilate_attn_kernel(const float* __restrict__ q,
                        const float* __restrict__ k,
                        const float* __restrict__ v,
                        float* __restrict__ out)
{
    const int gid  = blockIdx.x * NTHR + threadIdx.x;
    const int xg   = gid % XG;
    int r1         = gid / XG;
    const int y    = r1 % HT;
    int r2         = r1 / HT;
    const int head = r2 % HEADS;
    const int b    = r2 / HEADS;
    const int x0   = xg * 2;

    const int base = (b * CTOT + head * HD) * HW;
    const int pix  = y * WD + x0;

    const bool cL = (x0 >= 2);
    const bool cR = (x0 <= WD - 4);
    const bool yT = (y >= 2);
    const bool yB = (y <= HT - 3);

    // clamped offsets: invalid window -> load center (always valid), zero later
    int   voffc[9];
    float mf[9];
    {
        const bool vmask[9] = {
            yT && cL, yT, yT && cR,
            cL,       true, cR,
            yB && cL, yB, yB && cR
        };
        const int voff[9] = {
            -2 * WD - 2, -2 * WD, -2 * WD + 2,
            -2,           0,       2,
             2 * WD - 2,  2 * WD,  2 * WD + 2
        };
#pragma unroll
        for (int p = 0; p < 9; p++) {
            voffc[p] = vmask[p] ? voff[p] : 0;
            mf[p]    = vmask[p] ? 1.0f : 0.0f;
        }
    }

    const float* qc = q + base + pix;
    const float* kc = k + base + pix;
    const float* vc = v + base + pix;

    const float scale = 0.17677669529663687f;  // 32^-0.5

    float a0[9], a1[9];
#pragma unroll
    for (int p = 0; p < 9; p++) { a0[p] = 0.0f; a1[p] = 0.0f; }

    // ================= K phase: logits, branchless, CC=8 =================
#pragma unroll
    for (int ch = 0; ch < NCH; ch++) {
        float2 qv[CC];
#pragma unroll
        for (int c = 0; c < CC; c++) {
            qv[c] = *(const float2*)(qc + (ch * CC + c) * HW);
            qv[c].x *= scale; qv[c].y *= scale;
        }

        const float* kb = kc + ch * CC * HW;
#pragma unroll
        for (int p = 0; p < 9; p++) {
            const float* kp = kb + voffc[p];
            float s0 = a0[p], s1 = a1[p];
#pragma unroll
            for (int c = 0; c < CC; c++) {
                float2 kv = *(const float2*)(kp + c * HW);
                s0 = fmaf(qv[c].x, kv.x, s0);
                s1 = fmaf(qv[c].y, kv.y, s1);
            }
            a0[p] = s0; a1[p] = s1;
        }
    }

    // zero logits of invalid windows (unfold zero-padding -> logit exactly 0)
#pragma unroll
    for (int p = 0; p < 9; p++) { a0[p] *= mf[p]; a1[p] *= mf[p]; }

    // ================= softmax (normalization folded into weights) =================
    {
        float m0 = -1e30f, m1 = -1e30f;
#pragma unroll
        for (int p = 0; p < 9; p++) { m0 = fmaxf(m0, a0[p]); m1 = fmaxf(m1, a1[p]); }
        float d0 = 0.0f, d1 = 0.0f;
#pragma unroll
        for (int p = 0; p < 9; p++) {
            a0[p] = __expf(a0[p] - m0); d0 += a0[p];
            a1[p] = __expf(a1[p] - m1); d1 += a1[p];
        }
        float i0 = 1.0f / d0, i1 = 1.0f / d1;
        // re-mask: OOB neighbors have v == 0, so their weight contributes nothing
#pragma unroll
        for (int p = 0; p < 9; p++) {
            a0[p] *= i0 * mf[p];
            a1[p] *= i1 * mf[p];
        }
    }

    // ================= V phase: weighted sum, branchless + direct stores =================
    const int ob = ((b * HT + y) * WD + x0) * CTOT + head * HD;

#pragma unroll
    for (int ch = 0; ch < NCH; ch++) {
        float acc0[CC], acc1[CC];
#pragma unroll
        for (int c = 0; c < CC; c++) { acc0[c] = 0.0f; acc1[c] = 0.0f; }

        const float* vb = vc + ch * CC * HW;
#pragma unroll
        for (int p = 0; p < 9; p++) {
            const float w0 = a0[p], w1 = a1[p];
            const float* vp = vb + voffc[p];
#pragma unroll
            for (int c = 0; c < CC; c++) {
                float2 vv = *(const float2*)(vp + c * HW);
                acc0[c] = fmaf(w0, vv.x, acc0[c]);
                acc1[c] = fmaf(w1, vv.y, acc1[c]);
            }
        }

        float* o0 = out + ob + ch * CC;
        *(float4*)(o0)            = make_float4(acc0[0], acc0[1], acc0[2], acc0[3]);
        *(float4*)(o0 + 4)        = make_float4(acc0[4], acc0[5], acc0[6], acc0[7]);
        *(float4*)(o0 + CTOT)     = make_float4(acc1[0], acc1[1], acc1[2], acc1[3]);
        *(float4*)(o0 + CTOT + 4) = make_float4(acc1[4], acc1[5], acc1[6], acc1[7]);
    }
}

extern "C" void kernel_launch(void* const* d_in, const int* in_sizes, int n_in,
                              void* d_out, int out_size)
{
    const float* q = (const float*)d_in[0];
    const float* k = (const float*)d_in[1];
    const float* v = (const float*)d_in[2];
    float* out = (float*)d_out;

    int total  = BD * HEADS * HT * XG;   // 150528 threads (2 px each)
    int blocks = total / NTHR;           // 1176
    dilate_attn_kernel<<<blocks, NTHR>>>(q, k, v, out);
}

// round 11
// speedup vs baseline: 1.1405x; 1.1405x over previous
#include <cuda_runtime.h>

// DilateAttention: B=8, C=384 (12 heads x 32), H=W=56, kernel 3x3, dilation 2, pad 2.
// q,k,v: [B, C, H, W] f32. out: [B, H, W, C] f32.
//
// R11 = R7 (2 px/thread, float2 window loads, CC=8 chunks, 64-reg budget) with:
//  - 128-thread blocks -> 1176 blocks (8 resident/SM + turnover; fixes R7's
//    single-wave tail where grid/148 = 3.97)
//  - guards at ROW granularity (3 nearly-warp-uniform y-tests instead of 9
//    per-window tests); the 3 windows of a row live in one basic block so
//    ptxas can batch up to 24 loads. x-edge OOB (2 lanes/warp, 6 windows max)
//    handled branchlessly: clamped x-offset + post-hoc zero mask on logits
//    and on softmax weights (OOB neighbor value is 0 in the reference).

#define HD     32
#define HEADS  12
#define WD     56
#define HT     56
#define BD     8
#define HW     (WD * HT)
#define CTOT   384
#define XG     28          // x-pairs per row
#define NTHR   128
#define CC     8
#define NCH    (HD / CC)   // 4

__global__ __launch_bounds__(NTHR, 8)
void dilate_attn_kernel(const float* __restrict__ q,
                        const float* __restrict__ k,
                        const float* __restrict__ v,
                        float* __restrict__ out)
{
    const int gid  = blockIdx.x * NTHR + threadIdx.x;
    const int xg   = gid % XG;
    int r1         = gid / XG;
    const int y    = r1 % HT;
    int r2         = r1 / HT;
    const int head = r2 % HEADS;
    const int b    = r2 / HEADS;
    const int x0   = xg * 2;

    const int base = (b * CTOT + head * HD) * HW;
    const int pix  = y * WD + x0;

    const bool cL = (x0 >= 2);
    const bool cR = (x0 <= WD - 4);
    const bool yT = (y >= 2);
    const bool yB = (y <= HT - 3);

    // clamped x offsets for the 2 edge lanes (center column always valid)
    const int xL = cL ? -2 : 0;
    const int xR = cR ?  2 : 0;
    const float mL = cL ? 1.0f : 0.0f;
    const float mR = cR ? 1.0f : 0.0f;

    const float* qc = q + base + pix;
    const float* kc = k + base + pix;
    const float* vc = v + base + pix;

    const float scale = 0.17677669529663687f;  // 32^-0.5

    float a0[9], a1[9];
#pragma unroll
    for (int p = 0; p < 9; p++) { a0[p] = 0.0f; a1[p] = 0.0f; }

    // ================= K phase: logits, row-grouped, CC=8 =================
#pragma unroll
    for (int ch = 0; ch < NCH; ch++) {
        float2 qv[CC];
#pragma unroll
        for (int c = 0; c < CC; c++) {
            qv[c] = *(const float2*)(qc + (ch * CC + c) * HW);
            qv[c].x *= scale; qv[c].y *= scale;
        }
        const float* kb = kc + ch * CC * HW;

        // center row (always valid): windows 3,4,5
        {
            const float* kr = kb;
            float s0L = a0[3], s1L = a1[3], s0C = a0[4], s1C = a1[4], s0R = a0[5], s1R = a1[5];
#pragma unroll
            for (int c = 0; c < CC; c++) {
                float2 L = *(const float2*)(kr + c * HW + xL);
                float2 C = *(const float2*)(kr + c * HW);
                float2 R = *(const float2*)(kr + c * HW + xR);
                s0L = fmaf(qv[c].x, L.x, s0L); s1L = fmaf(qv[c].y, L.y, s1L);
                s0C = fmaf(qv[c].x, C.x, s0C); s1C = fmaf(qv[c].y, C.y, s1C);
                s0R = fmaf(qv[c].x, R.x, s0R); s1R = fmaf(qv[c].y, R.y, s1R);
            }
            a0[3] = s0L; a1[3] = s1L; a0[4] = s0C; a1[4] = s1C; a0[5] = s0R; a1[5] = s1R;
        }
        // top row y-2: windows 0,1,2
        if (yT) {
            const float* kr = kb - 2 * WD;
            float s0L = a0[0], s1L = a1[0], s0C = a0[1], s1C = a1[1], s0R = a0[2], s1R = a1[2];
#pragma unroll
            for (int c = 0; c < CC; c++) {
                float2 L = *(const float2*)(kr + c * HW + xL);
                float2 C = *(const float2*)(kr + c * HW);
                float2 R = *(const float2*)(kr + c * HW + xR);
                s0L = fmaf(qv[c].x, L.x, s0L); s1L = fmaf(qv[c].y, L.y, s1L);
                s0C = fmaf(qv[c].x, C.x, s0C); s1C = fmaf(qv[c].y, C.y, s1C);
                s0R = fmaf(qv[c].x, R.x, s0R); s1R = fmaf(qv[c].y, R.y, s1R);
            }
            a0[0] = s0L; a1[0] = s1L; a0[1] = s0C; a1[1] = s1C; a0[2] = s0R; a1[2] = s1R;
        }
        // bottom row y+2: windows 6,7,8
        if (yB) {
            const float* kr = kb + 2 * WD;
            float s0L = a0[6], s1L = a1[6], s0C = a0[7], s1C = a1[7], s0R = a0[8], s1R = a1[8];
#pragma unroll
            for (int c = 0; c < CC; c++) {
                float2 L = *(const float2*)(kr + c * HW + xL);
                float2 C = *(const float2*)(kr + c * HW);
                float2 R = *(const float2*)(kr + c * HW + xR);
                s0L = fmaf(qv[c].x, L.x, s0L); s1L = fmaf(qv[c].y, L.y, s1L);
                s0C = fmaf(qv[c].x, C.x, s0C); s1C = fmaf(qv[c].y, C.y, s1C);
                s0R = fmaf(qv[c].x, R.x, s0R); s1R = fmaf(qv[c].y, R.y, s1R);
            }
            a0[6] = s0L; a1[6] = s1L; a0[7] = s0C; a1[7] = s1C; a0[8] = s0R; a1[8] = s1R;
        }
    }

    // zero x-edge logits (reference: zero-padded -> logit exactly 0)
#pragma unroll
    for (int r = 0; r < 3; r++) {
        a0[r * 3]     *= mL; a1[r * 3]     *= mL;
        a0[r * 3 + 2] *= mR; a1[r * 3 + 2] *= mR;
    }

    // ================= softmax (normalization folded into weights) =================
    {
        float m0 = -1e30f, m1 = -1e30f;
#pragma unroll
        for (int p = 0; p < 9; p++) { m0 = fmaxf(m0, a0[p]); m1 = fmaxf(m1, a1[p]); }
        float d0 = 0.0f, d1 = 0.0f;
#pragma unroll
        for (int p = 0; p < 9; p++) {
            a0[p] = __expf(a0[p] - m0); d0 += a0[p];
            a1[p] = __expf(a1[p] - m1); d1 += a1[p];
        }
        float i0 = 1.0f / d0, i1 = 1.0f / d1;
#pragma unroll
        for (int p = 0; p < 9; p++) { a0[p] *= i0; a1[p] *= i1; }
        // re-zero x-edge weights (their clamped v-load would add center*w)
#pragma unroll
        for (int r = 0; r < 3; r++) {
            a0[r * 3]     *= mL; a1[r * 3]     *= mL;
            a0[r * 3 + 2] *= mR; a1[r * 3 + 2] *= mR;
        }
    }

    // ================= V phase: weighted sum, row-grouped + direct stores =================
    const int ob = ((b * HT + y) * WD + x0) * CTOT + head * HD;

#pragma unroll
    for (int ch = 0; ch < NCH; ch++) {
        float acc0[CC], acc1[CC];
#pragma unroll
        for (int c = 0; c < CC; c++) { acc0[c] = 0.0f; acc1[c] = 0.0f; }

        const float* vb = vc + ch * CC * HW;

        // center row
        {
            const float* vr = vb;
#pragma unroll
            for (int c = 0; c < CC; c++) {
                float2 L = *(const float2*)(vr + c * HW + xL);
                float2 C = *(const float2*)(vr + c * HW);
                float2 R = *(const float2*)(vr + c * HW + xR);
                acc0[c] = fmaf(a0[3], L.x, fmaf(a0[4], C.x, fmaf(a0[5], R.x, acc0[c])));
                acc1[c] = fmaf(a1[3], L.y, fmaf(a1[4], C.y, fmaf(a1[5], R.y, acc1[c])));
            }
        }
        if (yT) {
            const float* vr = vb - 2 * WD;
#pragma unroll
            for (int c = 0; c < CC; c++) {
                float2 L = *(const float2*)(vr + c * HW + xL);
                float2 C = *(const float2*)(vr + c * HW);
                float2 R = *(const float2*)(vr + c * HW + xR);
                acc0[c] = fmaf(a0[0], L.x, fmaf(a0[1], C.x, fmaf(a0[2], R.x, acc0[c])));
                acc1[c] = fmaf(a1[0], L.y, fmaf(a1[1], C.y, fmaf(a1[2], R.y, acc1[c])));
            }
        }
        if (yB) {
            const float* vr = vb + 2 * WD;
#pragma unroll
            for (int c = 0; c < CC; c++) {
                float2 L = *(const float2*)(vr + c * HW + xL);
                float2 C = *(const float2*)(vr + c * HW);
                float2 R = *(const float2*)(vr + c * HW + xR);
                acc0[c] = fmaf(a0[6], L.x, fmaf(a0[7], C.x, fmaf(a0[8], R.x, acc0[c])));
                acc1[c] = fmaf(a1[6], L.y, fmaf(a1[7], C.y, fmaf(a1[8], R.y, acc1[c])));
            }
        }

        float* o0 = out + ob + ch * CC;
        *(float4*)(o0)            = make_float4(acc0[0], acc0[1], acc0[2], acc0[3]);
        *(float4*)(o0 + 4)        = make_float4(acc0[4], acc0[5], acc0[6], acc0[7]);
        *(float4*)(o0 + CTOT)     = make_float4(acc1[0], acc1[1], acc1[2], acc1[3]);
        *(float4*)(o0 + CTOT + 4) = make_float4(acc1[4], acc1[5], acc1[6], acc1[7]);
    }
}

extern "C" void kernel_launch(void* const* d_in, const int* in_sizes, int n_in,
                              void* d_out, int out_size)
{
    const float* q = (const float*)d_in[0];
    const float* k = (const float*)d_in[1];
    const float* v = (const float*)d_in[2];
    float* out = (float*)d_out;

    int total  = BD * HEADS * HT * XG;   // 150528 threads (2 px each)
    int blocks = total / NTHR;           // 1176
    dilate_attn_kernel<<<blocks, NTHR>>>(q, k, v, out);
}